// round 3
// baseline (speedup 1.0000x reference)
#include <cuda_runtime.h>
#include <cuda_bf16.h>
#include <float.h>
#include <math.h>

// Problem constants (fixed by the dataset)
#define N_TRAIN   65536
#define N_TEST    4096
#define DIM       512
#define KNN       5
#define N_CLASSES 10

// Tiling
#define BM 64
#define BN 128
#define BK 16
#define SPLITS 16
#define CHUNK (N_TRAIN / SPLITS)   // 4096
#define NT (CHUNK / BN)            // 32 n-tiles per CTA
#define KT (DIM / BK)              // 32 k-tiles

// Scratch (device globals: no allocation allowed)
__device__ float g_x2[N_TRAIN];
__device__ float g_pd[N_TEST * SPLITS * KNN];
__device__ int   g_pi[N_TEST * SPLITS * KNN];

// Insert (s,n) into ascending 5-list kept in registers. Strict '<' keeps
// earlier (lower-index) entries on ties.
#define INSERT5(dArr, iArr, sv, nv)                              \
  do {                                                           \
    float _s = (sv); int _n = (nv);                              \
    if (_s < dArr[4]) {                                          \
      _Pragma("unroll")                                          \
      for (int _p = 4; _p >= 0; _p--) {                          \
        if (_p > 0 && _s < dArr[_p - 1]) {                       \
          dArr[_p] = dArr[_p - 1]; iArr[_p] = iArr[_p - 1];      \
        } else { dArr[_p] = _s; iArr[_p] = _n; break; }          \
      }                                                          \
    }                                                            \
  } while (0)

// ---------------------------------------------------------------------------
// Kernel 1: per-train-row squared norms. 8 rows per CTA (1 warp / row).
// ---------------------------------------------------------------------------
__global__ void x2_kernel(const float* __restrict__ Xtr) {
    int row  = blockIdx.x * 8 + (threadIdx.x >> 5);
    int lane = threadIdx.x & 31;
    const float4* p = reinterpret_cast<const float4*>(Xtr + (size_t)row * DIM);
    float s = 0.f;
#pragma unroll
    for (int i = 0; i < 4; i++) {
        float4 v = p[lane + 32 * i];
        s += v.x * v.x + v.y * v.y + v.z * v.z + v.w * v.w;
    }
#pragma unroll
    for (int o = 16; o; o >>= 1) s += __shfl_xor_sync(0xFFFFFFFFu, s, o);
    if (lane == 0) g_x2[row] = s;
}

// ---------------------------------------------------------------------------
// Kernel 2: fused distance-GEMM + per-split top-5.
// Grid: (N_TEST/BM, SPLITS). 256 threads, 4x8 register tile.
// Score s = x2[n] - 2 * dot(test_m, train_n)   (same ordering as distance).
// ---------------------------------------------------------------------------
__global__ void __launch_bounds__(256, 2)
knn_kernel(const float* __restrict__ Xtr, const float* __restrict__ Xte) {
    // Shared: GEMM tiles aliased with the merge buffer (disjoint in time).
    __shared__ __align__(16) float smem[10240];
    float (*As)[BM + 4] = reinterpret_cast<float (*)[BM + 4]>(smem);
    float (*Bs)[BN + 4] = reinterpret_cast<float (*)[BN + 4]>(smem + 1088);
    float* x2s = smem + 1088 + 2112;

    const int tid = threadIdx.x;
    const int tx  = tid & 15;   // n-group (8 cols each)
    const int ty  = tid >> 4;   // m-group (4 rows each)

    const int m0     = blockIdx.x * BM;
    const int n0base = blockIdx.y * CHUNK;

    float bd[4][5];
    int   bi[4][5];
#pragma unroll
    for (int i = 0; i < 4; i++)
#pragma unroll
        for (int q = 0; q < 5; q++) { bd[i][q] = FLT_MAX; bi[i][q] = 0x7FFFFFFF; }

    for (int nt = 0; nt < NT; nt++) {
        const int n0 = n0base + nt * BN;
        if (tid < BN) x2s[tid] = g_x2[n0 + tid];

        float acc[4][8];
#pragma unroll
        for (int i = 0; i < 4; i++)
#pragma unroll
            for (int j = 0; j < 8; j++) acc[i][j] = 0.f;

        for (int kt = 0; kt < KT; kt++) {
            const int k0 = kt * BK;
            // Load A tile (64 x 16): one float4 per thread, store transposed.
            {
                int row = tid >> 2, c4 = tid & 3;
                float4 v = *reinterpret_cast<const float4*>(
                    Xte + (size_t)(m0 + row) * DIM + k0 + c4 * 4);
                As[c4 * 4 + 0][row] = v.x;
                As[c4 * 4 + 1][row] = v.y;
                As[c4 * 4 + 2][row] = v.z;
                As[c4 * 4 + 3][row] = v.w;
            }
            // Load B tile (128 x 16): two float4 per thread, store transposed.
            {
                int r = tid >> 1;
#pragma unroll
                for (int e = 0; e < 2; e++) {
                    int c4 = (tid & 1) * 2 + e;
                    float4 v = *reinterpret_cast<const float4*>(
                        Xtr + (size_t)(n0 + r) * DIM + k0 + c4 * 4);
                    Bs[c4 * 4 + 0][r] = v.x;
                    Bs[c4 * 4 + 1][r] = v.y;
                    Bs[c4 * 4 + 2][r] = v.z;
                    Bs[c4 * 4 + 3][r] = v.w;
                }
            }
            __syncthreads();
#pragma unroll
            for (int k = 0; k < BK; k++) {
                float a[4], b[8];
                *reinterpret_cast<float4*>(a) =
                    *reinterpret_cast<const float4*>(&As[k][ty * 4]);
                *reinterpret_cast<float4*>(b) =
                    *reinterpret_cast<const float4*>(&Bs[k][tx * 8]);
                *reinterpret_cast<float4*>(b + 4) =
                    *reinterpret_cast<const float4*>(&Bs[k][tx * 8 + 4]);
#pragma unroll
                for (int i = 0; i < 4; i++)
#pragma unroll
                    for (int j = 0; j < 8; j++)
                        acc[i][j] = fmaf(a[i], b[j], acc[i][j]);
            }
            __syncthreads();
        }
        // Consume tile: score + top-5 insert.
#pragma unroll
        for (int j = 0; j < 8; j++) {
            const int   nidx = n0 + tx * 8 + j;
            const float xx   = x2s[tx * 8 + j];
#pragma unroll
            for (int i = 0; i < 4; i++) {
                float s = fmaf(-2.f, acc[i][j], xx);
                INSERT5(bd[i], bi[i], s, nidx);
            }
        }
        __syncthreads();   // protect x2s before next iteration rewrites it
    }

    // CTA merge: 16 thread-lists of 5 -> one list of 5 per test row.
    float* md = smem;                                   // [64][16][5]
    int*   mi = reinterpret_cast<int*>(smem + 5120);    // [64][16][5]
    __syncthreads();
#pragma unroll
    for (int i = 0; i < 4; i++) {
        int row = ty * 4 + i;
#pragma unroll
        for (int q = 0; q < 5; q++) {
            md[(row * 16 + tx) * 5 + q] = bd[i][q];
            mi[(row * 16 + tx) * 5 + q] = bi[i][q];
        }
    }
    __syncthreads();
    if (tid < BM) {
        float d[5]; int ix[5];
#pragma unroll
        for (int q = 0; q < 5; q++) { d[q] = FLT_MAX; ix[q] = 0x7FFFFFFF; }
        for (int t = 0; t < 16; t++) {
#pragma unroll
            for (int q = 0; q < 5; q++) {
                float s = md[(tid * 16 + t) * 5 + q];
                if (s >= d[4]) break;   // each sub-list ascending
                INSERT5(d, ix, s, mi[(tid * 16 + t) * 5 + q]);
            }
        }
        const int grow = m0 + tid;
        const int base = (grow * SPLITS + blockIdx.y) * KNN;
#pragma unroll
        for (int q = 0; q < 5; q++) { g_pd[base + q] = d[q]; g_pi[base + q] = ix[q]; }
    }
}

// ---------------------------------------------------------------------------
// Kernel 3: merge splits, gather labels, mode (smallest label wins ties).
// Output buffer is FLOAT32 (evidence: integer writes read back as ~0 ->
// rel_err exactly 1.0). Label dtype is detected at runtime from the bit
// pattern of the first 32 words:
//   int64 layout: odd 32-bit words all zero, even words in [0,9]
//   int32 layout: all words in [0,9]
//   float32     : words are f32 bit patterns of small integers
// ---------------------------------------------------------------------------
__global__ void finalize_kernel(const unsigned* __restrict__ yw,
                                float* __restrict__ out) {
    const int row = blockIdx.x * 256 + threadIdx.x;
    if (row >= N_TEST) return;

    // --- label dtype detection (same result in every thread; L2-cached) ---
    bool i32ok = true, i64ok = true, f32ok = true;
#pragma unroll
    for (int i = 0; i < 32; i++) {
        unsigned w = yw[i];
        if (w > 9u) i32ok = false;
        if (i & 1) { if (w != 0u) i64ok = false; }
        else       { if (w > 9u)  i64ok = false; }
        float f = __uint_as_float(w);
        if (!(f >= 0.f && f <= 9.f && f == floorf(f))) f32ok = false;
    }
    const int ymode = i64ok ? 1 : (i32ok ? 0 : (f32ok ? 2 : 0));

    float d[5]; int ix[5];
#pragma unroll
    for (int q = 0; q < 5; q++) { d[q] = FLT_MAX; ix[q] = 0x7FFFFFFF; }

    for (int s = 0; s < SPLITS; s++) {
        const int base = (row * SPLITS + s) * KNN;
#pragma unroll
        for (int q = 0; q < 5; q++) {
            float v = g_pd[base + q];
            if (v >= d[4]) break;      // per-split lists ascending
            INSERT5(d, ix, v, g_pi[base + q]);
        }
    }

    int lab[5];
#pragma unroll
    for (int q = 0; q < 5; q++) {
        unsigned w = (ymode == 1) ? yw[2 * (size_t)ix[q]] : yw[ix[q]];
        lab[q] = (ymode == 2) ? (int)__uint_as_float(w) : (int)w;
    }

    int best = 0x7FFFFFFF, bc = 0;
#pragma unroll
    for (int q = 0; q < 5; q++) {
        int c = 0;
#pragma unroll
        for (int r = 0; r < 5; r++) c += (lab[r] == lab[q]);
        if (c > bc || (c == bc && lab[q] < best)) { bc = c; best = lab[q]; }
    }
    out[row] = (float)best;
}

// ---------------------------------------------------------------------------
extern "C" void kernel_launch(void* const* d_in, const int* in_sizes, int n_in,
                              void* d_out, int out_size) {
    const float*    Xtr = (const float*)d_in[0];     // [65536, 512] f32
    const float*    Xte = (const float*)d_in[1];     // [4096, 512]  f32
    const unsigned* yw  = (const unsigned*)d_in[2];  // labels, dtype detected
    float*          out = (float*)d_out;             // [4096] f32 predictions

    x2_kernel<<<N_TRAIN / 8, 256>>>(Xtr);
    knn_kernel<<<dim3(N_TEST / BM, SPLITS), 256>>>(Xtr, Xte);
    finalize_kernel<<<N_TEST / 256, 256>>>(yw, out);
}

// round 5
// speedup vs baseline: 2.5897x; 2.5897x over previous
#include <cuda_runtime.h>
#include <cuda_bf16.h>
#include <float.h>
#include <math.h>
#include <stdint.h>

// ---------------- problem constants ----------------
#define N_TRAIN 65536
#define N_TEST  4096
#define DIM     512
#define KNN     5
#define SPLITS  8
#define TPS     (N_TRAIN / SPLITS)   // 8192 train rows per split
#define NTILES  (TPS / 128)          // 64 n-tiles per CTA
#define CAND    16                   // per-split candidate depth
#define SEL     20                   // rescored candidates per row

// ---------------- device scratch (no allocation allowed) ----------------
__device__ __nv_bfloat16 g_xtr_bf[(size_t)N_TRAIN * DIM];   // 64 MB
__device__ __nv_bfloat16 g_xte_bf[(size_t)N_TEST * DIM];    // 4 MB
__device__ float g_x2[N_TRAIN];
__device__ float g_cd[N_TEST * SPLITS * CAND];
__device__ int   g_ci[N_TEST * SPLITS * CAND];

// ---------------- smem layout (bytes) ----------------
#define A_STRIDE 1040                       // (512+8) bf16 per row
#define B_STRIDE 80                         // (32+8) bf16 per row
#define SM_A   0                            // 128*1040 = 133120
#define SM_B   133120                       // 2 * 128*80 = 20480
#define SM_SC  153600                       // scores 128*65*4 = 33280
#define SM_X2  186880                       // 512
#define SM_SD  187392                       // 256*17*4 = 17408
#define SM_SI  204800                       // 17408
#define SMEM_TOTAL 222208

__device__ __forceinline__ uint32_t smem_u32(const void* p) {
    uint32_t a;
    asm("{ .reg .u64 t; cvta.to.shared.u64 t, %1; cvt.u32.u64 %0, t; }"
        : "=r"(a) : "l"(p));
    return a;
}
#define CP_ASYNC16(dst, src) \
    asm volatile("cp.async.cg.shared.global [%0], [%1], 16;" :: "r"(dst), "l"(src))
#define CP_COMMIT() asm volatile("cp.async.commit_group;" ::: "memory")
#define CP_WAIT0()  asm volatile("cp.async.wait_group 0;" ::: "memory")

#define LDMATRIX_X4(r0, r1, r2, r3, addr)                                  \
    asm volatile("ldmatrix.sync.aligned.m8n8.x4.shared.b16 "               \
                 "{%0,%1,%2,%3}, [%4];"                                    \
                 : "=r"(r0), "=r"(r1), "=r"(r2), "=r"(r3) : "r"(addr))

#define MMA16816(c, a, b0, b1)                                             \
    asm volatile("mma.sync.aligned.m16n8k16.row.col.f32.bf16.bf16.f32 "    \
                 "{%0,%1,%2,%3}, {%4,%5,%6,%7}, {%8,%9}, {%0,%1,%2,%3};"   \
                 : "+f"((c)[0]), "+f"((c)[1]), "+f"((c)[2]), "+f"((c)[3])  \
                 : "r"((a)[0]), "r"((a)[1]), "r"((a)[2]), "r"((a)[3]),     \
                   "r"(b0), "r"(b1))

// ---------------------------------------------------------------------------
// Kernel 1a: convert train rows to bf16 + squared norms. 1 warp per row.
// ---------------------------------------------------------------------------
__global__ void conv_train_kernel(const float* __restrict__ X) {
    int row  = blockIdx.x * 8 + (threadIdx.x >> 5);
    int lane = threadIdx.x & 31;
    const float4* p = reinterpret_cast<const float4*>(X + (size_t)row * DIM);
    uint2* o = reinterpret_cast<uint2*>(g_xtr_bf + (size_t)row * DIM);
    float s = 0.f;
#pragma unroll
    for (int i = 0; i < 4; i++) {
        float4 v = p[lane + 32 * i];
        s += v.x * v.x + v.y * v.y + v.z * v.z + v.w * v.w;
        __nv_bfloat162 b0 = __float22bfloat162_rn(make_float2(v.x, v.y));
        __nv_bfloat162 b1 = __float22bfloat162_rn(make_float2(v.z, v.w));
        uint2 w;
        w.x = *reinterpret_cast<uint32_t*>(&b0);
        w.y = *reinterpret_cast<uint32_t*>(&b1);
        o[lane + 32 * i] = w;
    }
#pragma unroll
    for (int off = 16; off; off >>= 1) s += __shfl_xor_sync(0xFFFFFFFFu, s, off);
    if (lane == 0) g_x2[row] = s;
}

__global__ void conv_test_kernel(const float* __restrict__ X) {
    int row  = blockIdx.x * 8 + (threadIdx.x >> 5);
    int lane = threadIdx.x & 31;
    const float4* p = reinterpret_cast<const float4*>(X + (size_t)row * DIM);
    uint2* o = reinterpret_cast<uint2*>(g_xte_bf + (size_t)row * DIM);
#pragma unroll
    for (int i = 0; i < 4; i++) {
        float4 v = p[lane + 32 * i];
        __nv_bfloat162 b0 = __float22bfloat162_rn(make_float2(v.x, v.y));
        __nv_bfloat162 b1 = __float22bfloat162_rn(make_float2(v.z, v.w));
        uint2 w;
        w.x = *reinterpret_cast<uint32_t*>(&b0);
        w.y = *reinterpret_cast<uint32_t*>(&b1);
        o[lane + 32 * i] = w;
    }
}

// ---------------------------------------------------------------------------
// Kernel 2: bf16 mma.sync distance GEMM + fused per-row top-16 candidates.
// Grid (32 m-tiles, 8 splits). 256 threads = 8 warps: warp (wm = wid&3,
// wn = wid>>2) computes a 32x64 sub-tile of the 128x128 score tile.
// A (test tile 128x512 bf16) resident in smem; B double-buffered cp.async.
// ---------------------------------------------------------------------------
__global__ void __launch_bounds__(256, 1)
knn_gemm_kernel() {
    extern __shared__ __align__(16) char smem[];
    const uint32_t sb = smem_u32(smem);

    const int tid  = threadIdx.x;
    const int wid  = tid >> 5;
    const int lane = tid & 31;
    const int wm   = wid & 3;
    const int wn   = wid >> 2;
    const int m0    = blockIdx.x * 128;
    const int split = blockIdx.y;
    const int nbase = split * TPS;

    float* scores = reinterpret_cast<float*>(smem + SM_SC);
    float* x2s    = reinterpret_cast<float*>(smem + SM_X2);
    float* sd     = reinterpret_cast<float*>(smem + SM_SD);
    int*   si     = reinterpret_cast<int*>(smem + SM_SI);

    // ---- load A resident (128 rows x 512 bf16, padded stride) ----
#pragma unroll
    for (int i = tid; i < 8192; i += 256) {   // 16B chunks: 128 rows x 64
        int row = i >> 6, c16 = i & 63;
        const char* src = (const char*)(g_xte_bf + (size_t)(m0 + row) * DIM + c16 * 8);
        CP_ASYNC16(sb + SM_A + row * A_STRIDE + c16 * 16, src);
    }
    CP_COMMIT();

    // ---- init candidate lists ----
    const int lbase = tid * 17;
#pragma unroll
    for (int q = 0; q < CAND; q++) { sd[lbase + q] = FLT_MAX; si[lbase + q] = 0x7FFFFFFF; }
    float worst = FLT_MAX;

    // ---- ldmatrix lane address components ----
    // A frag (m16k16): lanes 0-7 rows0-7 k0 | 8-15 rows8-15 k0 | 16-23 rows0-7 k8 | 24-31 rows8-15 k8
    const uint32_t a_lane = sb + SM_A +
        (uint32_t)(wm * 32 + (lane & 7) + ((lane >> 3) & 1) * 8) * A_STRIDE +
        (uint32_t)(lane >> 4) * 16;
    // B frag pair (two n-frags): lanes 0-7 n0-7 k0 | 8-15 n0-7 k8 | 16-23 n8-15 k0 | 24-31 n8-15 k8
    const uint32_t b_row  = (lane & 7) + (lane >> 4) * 8;
    const uint32_t b_koff = ((lane >> 3) & 1) * 16;

    // ---- B chunk loader: 128 rows x 64B per chunk g (nt = g>>4, kt = g&15) ----
    auto load_chunk = [&](int g) {
        if (g >= NTILES * 16) return;
        const int ntc = g >> 4, ktc = g & 15;
        const uint32_t dbase = sb + SM_B + (uint32_t)(g & 1) * 10240;
#pragma unroll
        for (int e = 0; e < 2; e++) {
            int id  = tid * 2 + e;
            int row = id >> 2, c16 = id & 3;
            const char* src = (const char*)(g_xtr_bf +
                (size_t)(nbase + ntc * 128 + row) * DIM + ktc * 32 + c16 * 8);
            CP_ASYNC16(dbase + row * B_STRIDE + c16 * 16, src);
        }
        CP_COMMIT();
    };
    load_chunk(0);

    for (int nt = 0; nt < NTILES; nt++) {
        const int n0 = nbase + nt * 128;
        if (tid < 128) x2s[tid] = g_x2[n0 + tid];

        float acc[2][8][4];
#pragma unroll
        for (int mi = 0; mi < 2; mi++)
#pragma unroll
            for (int ni = 0; ni < 8; ni++)
#pragma unroll
                for (int j = 0; j < 4; j++) acc[mi][ni][j] = 0.f;

        for (int kt = 0; kt < 16; kt++) {
            const int g = nt * 16 + kt;
            CP_WAIT0();
            __syncthreads();
            load_chunk(g + 1);   // prefetch next chunk (or next tile's chunk 0)

            const uint32_t bbuf = sb + SM_B + (uint32_t)(g & 1) * 10240;
#pragma unroll
            for (int ks = 0; ks < 2; ks++) {
                const uint32_t kb = (uint32_t)kt * 64 + (uint32_t)ks * 32;  // bytes in A row
                uint32_t a[2][4];
#pragma unroll
                for (int mi = 0; mi < 2; mi++)
                    LDMATRIX_X4(a[mi][0], a[mi][1], a[mi][2], a[mi][3],
                                a_lane + (uint32_t)mi * 16 * A_STRIDE + kb);
                uint32_t b[4][4];
#pragma unroll
                for (int np = 0; np < 4; np++)
                    LDMATRIX_X4(b[np][0], b[np][1], b[np][2], b[np][3],
                                bbuf + (uint32_t)(wn * 64 + np * 16 + b_row) * B_STRIDE +
                                (uint32_t)ks * 32 + b_koff);
#pragma unroll
                for (int mi = 0; mi < 2; mi++)
#pragma unroll
                    for (int np = 0; np < 4; np++) {
                        MMA16816(acc[mi][np * 2 + 0], a[mi], b[np][0], b[np][1]);
                        MMA16816(acc[mi][np * 2 + 1], a[mi], b[np][2], b[np][3]);
                    }
            }
        }

        // ---- epilogue in two 64-col halves through smem ----
#pragma unroll
        for (int h = 0; h < 2; h++) {
            if (wn == h) {
                const int r0 = wm * 32 + (lane >> 2);
#pragma unroll
                for (int mi = 0; mi < 2; mi++)
#pragma unroll
                    for (int ni = 0; ni < 8; ni++) {
                        const int cl = ni * 8 + 2 * (lane & 3);
                        const int cg = h * 64 + cl;
                        const int r  = r0 + mi * 16;
                        scores[r * 65 + cl]           = fmaf(-2.f, acc[mi][ni][0], x2s[cg]);
                        scores[r * 65 + cl + 1]       = fmaf(-2.f, acc[mi][ni][1], x2s[cg + 1]);
                        scores[(r + 8) * 65 + cl]     = fmaf(-2.f, acc[mi][ni][2], x2s[cg]);
                        scores[(r + 8) * 65 + cl + 1] = fmaf(-2.f, acc[mi][ni][3], x2s[cg + 1]);
                    }
            }
            __syncthreads();
            // scan: 2 threads per row, 32 cols each; bank = (row + c) mod 32.
            const int row  = tid & 127;
            const int part = tid >> 7;
#pragma unroll 4
            for (int c = 0; c < 32; c++) {
                const int cl = part * 32 + c;
                const float s = scores[row * 65 + cl];
                if (s < worst) {
                    const int n = n0 + h * 64 + cl;
                    int p = CAND - 1;
#pragma unroll 1
                    while (p > 0 && sd[lbase + p - 1] > s) {
                        sd[lbase + p] = sd[lbase + p - 1];
                        si[lbase + p] = si[lbase + p - 1];
                        --p;
                    }
                    sd[lbase + p] = s; si[lbase + p] = n;
                    worst = sd[lbase + CAND - 1];
                }
            }
            __syncthreads();
        }
    }

    // ---- merge the two per-row lists, write candidates ----
    if (tid < 128) {
        const int b0 = tid * 17, b1 = (tid + 128) * 17;
        int i = 0, j = 0;
        const size_t ob = (size_t)(m0 + tid) * (SPLITS * CAND) + (size_t)split * CAND;
#pragma unroll
        for (int q = 0; q < CAND; q++) {
            const float s0 = sd[b0 + i], s1 = sd[b1 + j];
            const bool t0 = (s0 < s1) || (s0 == s1 && si[b0 + i] <= si[b1 + j]);
            if (t0) { g_cd[ob + q] = s0; g_ci[ob + q] = si[b0 + i]; i++; }
            else    { g_cd[ob + q] = s1; g_ci[ob + q] = si[b1 + j]; j++; }
        }
    }
}

// ---------------------------------------------------------------------------
// Kernel 3: rescue + finalize. One warp per test row.
// ---------------------------------------------------------------------------
__global__ void rescue_kernel(const float* __restrict__ Xtr,
                              const float* __restrict__ Xte,
                              const unsigned* __restrict__ yw,
                              float* __restrict__ out) {
    const int m    = blockIdx.x * 8 + (threadIdx.x >> 5);
    const int lane = threadIdx.x & 31;
    if (m >= N_TEST) return;

    // label dtype detection (uniform across threads)
    bool i32ok = true, i64ok = true, f32ok = true;
#pragma unroll
    for (int i = 0; i < 32; i++) {
        unsigned w = yw[i];
        if (w > 9u) i32ok = false;
        if (i & 1) { if (w != 0u) i64ok = false; }
        else       { if (w > 9u)  i64ok = false; }
        float f = __uint_as_float(w);
        if (!(f >= 0.f && f <= 9.f && f == floorf(f))) f32ok = false;
    }
    const int ymode = i64ok ? 1 : (i32ok ? 0 : (f32ok ? 2 : 0));

    // load 128 merged candidates: 4 per lane
    float cs[4]; int ci_[4];
    const size_t cb = (size_t)m * (SPLITS * CAND);
#pragma unroll
    for (int e = 0; e < 4; e++) {
        cs[e]  = g_cd[cb + lane + 32 * e];
        ci_[e] = g_ci[cb + lane + 32 * e];
    }

    // select top-SEL by bf16 score (repeated warp argmin)
    int sel[SEL];
#pragma unroll
    for (int it = 0; it < SEL; it++) {
        float bs = cs[0]; int be = 0;
#pragma unroll
        for (int e = 1; e < 4; e++)
            if (cs[e] < bs) { bs = cs[e]; be = e; }
        int pl = lane * 4 + be;
#pragma unroll
        for (int off = 16; off; off >>= 1) {
            float os = __shfl_xor_sync(0xFFFFFFFFu, bs, off);
            int   op = __shfl_xor_sync(0xFFFFFFFFu, pl, off);
            if (os < bs || (os == bs && op < pl)) { bs = os; pl = op; }
        }
        const int wl = pl >> 2, we = pl & 3;
        int v = (we == 0) ? ci_[0] : (we == 1) ? ci_[1] : (we == 2) ? ci_[2] : ci_[3];
        sel[it] = __shfl_sync(0xFFFFFFFFu, v, wl);
        if (lane == wl) {
            if (we == 0) cs[0] = FLT_MAX;
            else if (we == 1) cs[1] = FLT_MAX;
            else if (we == 2) cs[2] = FLT_MAX;
            else cs[3] = FLT_MAX;
        }
    }

    // exact fp32 rescore of the SEL candidates
    float a[16];
    {
        const float4* tp = reinterpret_cast<const float4*>(
            Xte + (size_t)m * DIM + lane * 16);
#pragma unroll
        for (int u = 0; u < 4; u++) {
            float4 v = tp[u];
            a[u * 4 + 0] = v.x; a[u * 4 + 1] = v.y;
            a[u * 4 + 2] = v.z; a[u * 4 + 3] = v.w;
        }
    }
    float my_s = FLT_MAX; int my_i = 0x7FFFFFFF;
#pragma unroll
    for (int t = 0; t < SEL; t++) {
        const int idx = sel[t];
        const float4* rp = reinterpret_cast<const float4*>(
            Xtr + (size_t)idx * DIM + lane * 16);
        float dot = 0.f;
#pragma unroll
        for (int u = 0; u < 4; u++) {
            float4 v = rp[u];
            dot = fmaf(a[u * 4 + 0], v.x, dot);
            dot = fmaf(a[u * 4 + 1], v.y, dot);
            dot = fmaf(a[u * 4 + 2], v.z, dot);
            dot = fmaf(a[u * 4 + 3], v.w, dot);
        }
#pragma unroll
        for (int off = 16; off; off >>= 1)
            dot += __shfl_xor_sync(0xFFFFFFFFu, dot, off);
        const float s = fmaf(-2.f, dot, __ldg(&g_x2[idx]));
        if (lane == t) { my_s = s; my_i = idx; }
    }

    // top-5 by (score, index), gather labels, mode
    int lab[5];
#pragma unroll
    for (int r = 0; r < 5; r++) {
        float bs = my_s; int bi = my_i;
#pragma unroll
        for (int off = 16; off; off >>= 1) {
            float os = __shfl_xor_sync(0xFFFFFFFFu, bs, off);
            int   oi = __shfl_xor_sync(0xFFFFFFFFu, bi, off);
            if (os < bs || (os == bs && oi < bi)) { bs = os; bi = oi; }
        }
        if (my_s == bs && my_i == bi) my_s = FLT_MAX;   // knock out winner
        unsigned w = (ymode == 1) ? yw[2 * (size_t)bi] : yw[bi];
        lab[r] = (ymode == 2) ? (int)__uint_as_float(w) : (int)w;
    }

    if (lane == 0) {
        int best = 0x7FFFFFFF, bc = 0;
#pragma unroll
        for (int q = 0; q < 5; q++) {
            int c = 0;
#pragma unroll
            for (int r = 0; r < 5; r++) c += (lab[r] == lab[q]);
            if (c > bc || (c == bc && lab[q] < best)) { bc = c; best = lab[q]; }
        }
        out[m] = (float)best;
    }
}

// ---------------------------------------------------------------------------
extern "C" void kernel_launch(void* const* d_in, const int* in_sizes, int n_in,
                              void* d_out, int out_size) {
    const float*    Xtr = (const float*)d_in[0];     // [65536, 512] f32
    const float*    Xte = (const float*)d_in[1];     // [4096, 512]  f32
    const unsigned* yw  = (const unsigned*)d_in[2];  // labels, dtype detected
    float*          out = (float*)d_out;             // [4096] f32 predictions

    cudaFuncSetAttribute(knn_gemm_kernel,
                         cudaFuncAttributeMaxDynamicSharedMemorySize, SMEM_TOTAL);

    conv_train_kernel<<<N_TRAIN / 8, 256>>>(Xtr);
    conv_test_kernel<<<N_TEST / 8, 256>>>(Xte);
    knn_gemm_kernel<<<dim3(N_TEST / 128, SPLITS), 256, SMEM_TOTAL>>>();
    rescue_kernel<<<N_TEST / 8, 256>>>(Xtr, Xte, yw, out);
}

// round 6
// speedup vs baseline: 5.5327x; 2.1364x over previous
#include <cuda_runtime.h>
#include <cuda_bf16.h>
#include <float.h>
#include <math.h>
#include <stdint.h>

// ---------------- problem constants ----------------
#define N_TRAIN 65536
#define N_TEST  4096
#define DIM     512
#define KNN     5
#define SPLITS  8
#define TPS     (N_TRAIN / SPLITS)   // 8192 train rows per split
#define NTILES  (TPS / 128)          // 64 n-tiles per CTA
#define CAND    8                    // per-thread candidate depth (2 thr/row)
#define SEL     20                   // rescored candidates per row

// ---------------- device scratch ----------------
__device__ __nv_bfloat16 g_xtr_bf[(size_t)N_TRAIN * DIM];   // 64 MB
__device__ __nv_bfloat16 g_xte_bf[(size_t)N_TEST * DIM];    // 4 MB
__device__ float g_x2[N_TRAIN];
__device__ float g_cd[N_TEST * SPLITS * 16];
__device__ int   g_ci[N_TEST * SPLITS * 16];

// ---------------- smem layout (bytes) ----------------
#define A_STRIDE 1040                       // (512+8) bf16 per row
#define B_STRIDE 144                        // 128 B data + 16 B pad
#define B_STAGE  (128 * B_STRIDE)           // 18432
#define SM_A   0                            // 128*1040 = 133120
#define SM_B   133120                       // 3 stages = 55296
#define SM_SC  188416                       // scores 128*65*4 = 33280
#define SM_X2  221696                       // 512
#define SMEM_TOTAL 222208

__device__ __forceinline__ uint32_t smem_u32(const void* p) {
    uint32_t a;
    asm("{ .reg .u64 t; cvta.to.shared.u64 t, %1; cvt.u32.u64 %0, t; }"
        : "=r"(a) : "l"(p));
    return a;
}
#define CP_ASYNC16(dst, src) \
    asm volatile("cp.async.cg.shared.global [%0], [%1], 16;" :: "r"(dst), "l"(src))
#define CP_COMMIT() asm volatile("cp.async.commit_group;" ::: "memory")
#define CP_WAIT1()  asm volatile("cp.async.wait_group 1;" ::: "memory")

#define LDMATRIX_X4(r0, r1, r2, r3, addr)                                  \
    asm volatile("ldmatrix.sync.aligned.m8n8.x4.shared.b16 "               \
                 "{%0,%1,%2,%3}, [%4];"                                    \
                 : "=r"(r0), "=r"(r1), "=r"(r2), "=r"(r3) : "r"(addr))

#define MMA16816(c, a, b0, b1)                                             \
    asm volatile("mma.sync.aligned.m16n8k16.row.col.f32.bf16.bf16.f32 "    \
                 "{%0,%1,%2,%3}, {%4,%5,%6,%7}, {%8,%9}, {%0,%1,%2,%3};"   \
                 : "+f"((c)[0]), "+f"((c)[1]), "+f"((c)[2]), "+f"((c)[3])  \
                 : "r"((a)[0]), "r"((a)[1]), "r"((a)[2]), "r"((a)[3]),     \
                   "r"(b0), "r"(b1))

// Register insertion into ascending CAND-list (fully unrolled ladder).
#define INSERT8(dA, iA, sv, nv)                                  \
  do {                                                           \
    float _s = (sv); int _n = (nv);                              \
    _Pragma("unroll")                                            \
    for (int _p = CAND - 1; _p >= 0; _p--) {                     \
      if (_p > 0 && _s < dA[_p - 1]) {                           \
        dA[_p] = dA[_p - 1]; iA[_p] = iA[_p - 1];                \
      } else { dA[_p] = _s; iA[_p] = _n; break; }                \
    }                                                            \
  } while (0)

// ---------------------------------------------------------------------------
// Kernel 1a/1b: bf16 conversion (+ norms for train). 1 warp per row.
// ---------------------------------------------------------------------------
__global__ void conv_train_kernel(const float* __restrict__ X) {
    int row  = blockIdx.x * 8 + (threadIdx.x >> 5);
    int lane = threadIdx.x & 31;
    const float4* p = reinterpret_cast<const float4*>(X + (size_t)row * DIM);
    uint2* o = reinterpret_cast<uint2*>(g_xtr_bf + (size_t)row * DIM);
    float s = 0.f;
#pragma unroll
    for (int i = 0; i < 4; i++) {
        float4 v = p[lane + 32 * i];
        s += v.x * v.x + v.y * v.y + v.z * v.z + v.w * v.w;
        __nv_bfloat162 b0 = __float22bfloat162_rn(make_float2(v.x, v.y));
        __nv_bfloat162 b1 = __float22bfloat162_rn(make_float2(v.z, v.w));
        uint2 w;
        w.x = *reinterpret_cast<uint32_t*>(&b0);
        w.y = *reinterpret_cast<uint32_t*>(&b1);
        o[lane + 32 * i] = w;
    }
#pragma unroll
    for (int off = 16; off; off >>= 1) s += __shfl_xor_sync(0xFFFFFFFFu, s, off);
    if (lane == 0) g_x2[row] = s;
}

__global__ void conv_test_kernel(const float* __restrict__ X) {
    int row  = blockIdx.x * 8 + (threadIdx.x >> 5);
    int lane = threadIdx.x & 31;
    const float4* p = reinterpret_cast<const float4*>(X + (size_t)row * DIM);
    uint2* o = reinterpret_cast<uint2*>(g_xte_bf + (size_t)row * DIM);
#pragma unroll
    for (int i = 0; i < 4; i++) {
        float4 v = p[lane + 32 * i];
        __nv_bfloat162 b0 = __float22bfloat162_rn(make_float2(v.x, v.y));
        __nv_bfloat162 b1 = __float22bfloat162_rn(make_float2(v.z, v.w));
        uint2 w;
        w.x = *reinterpret_cast<uint32_t*>(&b0);
        w.y = *reinterpret_cast<uint32_t*>(&b1);
        o[lane + 32 * i] = w;
    }
}

// ---------------------------------------------------------------------------
// Kernel 2: bf16 mma.sync GEMM + per-row top-8x2 candidates.
// 256 threads = 8 warps; warp (wm=wid&3, wn=wid>>2) owns 32x64 of 128x128.
// A resident in smem; B streamed in 128x64-elem chunks, 3-stage cp.async ring.
// ---------------------------------------------------------------------------
__global__ void __launch_bounds__(256, 1)
knn_gemm_kernel() {
    extern __shared__ __align__(16) char smem[];
    const uint32_t sb = smem_u32(smem);

    const int tid  = threadIdx.x;
    const int wid  = tid >> 5;
    const int lane = tid & 31;
    const int wm   = wid & 3;
    const int wn   = wid >> 2;
    const int m0    = blockIdx.x * 128;
    const int split = blockIdx.y;
    const int nbase = split * TPS;

    float* scores = reinterpret_cast<float*>(smem + SM_SC);
    float* x2s    = reinterpret_cast<float*>(smem + SM_X2);

    // ---- A resident (128 x 512 bf16), group 0 ----
#pragma unroll
    for (int i = tid; i < 8192; i += 256) {
        int row = i >> 6, c16 = i & 63;
        const char* src = (const char*)(g_xte_bf + (size_t)(m0 + row) * DIM + c16 * 8);
        CP_ASYNC16(sb + SM_A + row * A_STRIDE + c16 * 16, src);
    }
    CP_COMMIT();

    // ---- register candidate lists ----
    float cd[CAND]; int cix[CAND];
#pragma unroll
    for (int q = 0; q < CAND; q++) { cd[q] = FLT_MAX; cix[q] = 0x7FFFFFFF; }
    float worst = FLT_MAX;

    // ---- ldmatrix lane addresses ----
    const uint32_t a_lane = sb + SM_A +
        (uint32_t)(wm * 32 + (lane & 7) + ((lane >> 3) & 1) * 8) * A_STRIDE +
        (uint32_t)(lane >> 4) * 16;
    const uint32_t b_row  = (lane & 7) + (lane >> 4) * 8;
    const uint32_t b_koff = ((lane >> 3) & 1) * 16;

    // ---- B chunk loader: chunk g = (nt = g>>3, kt = g&7), 128 rows x 128 B ----
    auto load_chunk = [&](int g) {
        if (g < NTILES * 8) {
            const int ntc = g >> 3, ktc = g & 7;
            const uint32_t dbase = sb + SM_B + (uint32_t)(g % 3) * B_STAGE;
#pragma unroll
            for (int e = 0; e < 4; e++) {
                int id  = tid * 4 + e;
                int row = id >> 3, c16 = id & 7;
                const char* src = (const char*)(g_xtr_bf +
                    (size_t)(nbase + ntc * 128 + row) * DIM + ktc * 64 + c16 * 8);
                CP_ASYNC16(dbase + row * B_STRIDE + c16 * 16, src);
            }
        }
        CP_COMMIT();   // always commit (group accounting stays uniform)
    };
    load_chunk(0);
    load_chunk(1);

    for (int nt = 0; nt < NTILES; nt++) {
        const int n0 = nbase + nt * 128;
        if (tid < 128) x2s[tid] = g_x2[n0 + tid];

        float acc[2][8][4];
#pragma unroll
        for (int mi = 0; mi < 2; mi++)
#pragma unroll
            for (int ni = 0; ni < 8; ni++)
#pragma unroll
                for (int j = 0; j < 4; j++) acc[mi][ni][j] = 0.f;

        for (int kt = 0; kt < 8; kt++) {
            const int g = nt * 8 + kt;
            CP_WAIT1();          // chunk g complete (newest g+1 may be in flight)
            __syncthreads();     // all warps done with slot (g-1)%3
            load_chunk(g + 2);   // refill slot (g+2)%3 == (g-1)%3

            const uint32_t bbuf = sb + SM_B + (uint32_t)(g % 3) * B_STAGE;
#pragma unroll
            for (int ks = 0; ks < 4; ks++) {
                const uint32_t kb = (uint32_t)kt * 128 + (uint32_t)ks * 32;
                uint32_t a[2][4];
#pragma unroll
                for (int mi = 0; mi < 2; mi++)
                    LDMATRIX_X4(a[mi][0], a[mi][1], a[mi][2], a[mi][3],
                                a_lane + (uint32_t)mi * 16 * A_STRIDE + kb);
                uint32_t b[4][4];
#pragma unroll
                for (int np = 0; np < 4; np++)
                    LDMATRIX_X4(b[np][0], b[np][1], b[np][2], b[np][3],
                                bbuf + (uint32_t)(wn * 64 + np * 16 + b_row) * B_STRIDE +
                                (uint32_t)ks * 32 + b_koff);
#pragma unroll
                for (int mi = 0; mi < 2; mi++)
#pragma unroll
                    for (int np = 0; np < 4; np++) {
                        MMA16816(acc[mi][np * 2 + 0], a[mi], b[np][0], b[np][1]);
                        MMA16816(acc[mi][np * 2 + 1], a[mi], b[np][2], b[np][3]);
                    }
            }
        }

        // ---- epilogue: two 64-col halves through smem ----
#pragma unroll
        for (int h = 0; h < 2; h++) {
            if (wn == h) {
                const int r0 = wm * 32 + (lane >> 2);
#pragma unroll
                for (int mi = 0; mi < 2; mi++)
#pragma unroll
                    for (int ni = 0; ni < 8; ni++) {
                        const int cl = ni * 8 + 2 * (lane & 3);
                        const int cg = h * 64 + cl;
                        const int r  = r0 + mi * 16;
                        scores[r * 65 + cl]           = fmaf(-2.f, acc[mi][ni][0], x2s[cg]);
                        scores[r * 65 + cl + 1]       = fmaf(-2.f, acc[mi][ni][1], x2s[cg + 1]);
                        scores[(r + 8) * 65 + cl]     = fmaf(-2.f, acc[mi][ni][2], x2s[cg]);
                        scores[(r + 8) * 65 + cl + 1] = fmaf(-2.f, acc[mi][ni][3], x2s[cg + 1]);
                    }
            }
            __syncthreads();
            const int srow = tid & 127;
            const int part = tid >> 7;
#pragma unroll 4
            for (int c = 0; c < 32; c++) {
                const int cl = part * 32 + c;
                const float s = scores[srow * 65 + cl];
                if (s < worst) {
                    INSERT8(cd, cix, s, n0 + h * 64 + cl);
                    worst = cd[CAND - 1];
                }
            }
            __syncthreads();
        }
    }

    // ---- write out candidates: row gets 16 = two threads' 8-lists ----
    {
        const int row = tid & 127, part = tid >> 7;
        const size_t ob = (size_t)(m0 + row) * (SPLITS * 16) +
                          (size_t)split * 16 + part * CAND;
#pragma unroll
        for (int q = 0; q < CAND; q++) { g_cd[ob + q] = cd[q]; g_ci[ob + q] = cix[q]; }
    }
}

// ---------------------------------------------------------------------------
// Kernel 3: rescue + finalize. One warp per test row.
// ---------------------------------------------------------------------------
__global__ void rescue_kernel(const float* __restrict__ Xtr,
                              const float* __restrict__ Xte,
                              const unsigned* __restrict__ yw,
                              float* __restrict__ out) {
    const int m    = blockIdx.x * 8 + (threadIdx.x >> 5);
    const int lane = threadIdx.x & 31;
    if (m >= N_TEST) return;

    // label dtype detection (uniform across threads)
    bool i32ok = true, i64ok = true, f32ok = true;
#pragma unroll
    for (int i = 0; i < 32; i++) {
        unsigned w = yw[i];
        if (w > 9u) i32ok = false;
        if (i & 1) { if (w != 0u) i64ok = false; }
        else       { if (w > 9u)  i64ok = false; }
        float f = __uint_as_float(w);
        if (!(f >= 0.f && f <= 9.f && f == floorf(f))) f32ok = false;
    }
    const int ymode = i64ok ? 1 : (i32ok ? 0 : (f32ok ? 2 : 0));

    // load 128 candidates: 4 per lane
    float cs[4]; int ci_[4];
    const size_t cb = (size_t)m * (SPLITS * 16);
#pragma unroll
    for (int e = 0; e < 4; e++) {
        cs[e]  = g_cd[cb + lane + 32 * e];
        ci_[e] = g_ci[cb + lane + 32 * e];
    }

    // select top-SEL by bf16 score (repeated warp argmin)
    int sel[SEL];
#pragma unroll
    for (int it = 0; it < SEL; it++) {
        float bs = cs[0]; int be = 0;
#pragma unroll
        for (int e = 1; e < 4; e++)
            if (cs[e] < bs) { bs = cs[e]; be = e; }
        int pl = lane * 4 + be;
#pragma unroll
        for (int off = 16; off; off >>= 1) {
            float os = __shfl_xor_sync(0xFFFFFFFFu, bs, off);
            int   op = __shfl_xor_sync(0xFFFFFFFFu, pl, off);
            if (os < bs || (os == bs && op < pl)) { bs = os; pl = op; }
        }
        const int wl = pl >> 2, we = pl & 3;
        int v = (we == 0) ? ci_[0] : (we == 1) ? ci_[1] : (we == 2) ? ci_[2] : ci_[3];
        sel[it] = __shfl_sync(0xFFFFFFFFu, v, wl);
        if (lane == wl) {
            if (we == 0) cs[0] = FLT_MAX;
            else if (we == 1) cs[1] = FLT_MAX;
            else if (we == 2) cs[2] = FLT_MAX;
            else cs[3] = FLT_MAX;
        }
    }

    // exact fp32 rescore of the SEL candidates
    float a[16];
    {
        const float4* tp = reinterpret_cast<const float4*>(
            Xte + (size_t)m * DIM + lane * 16);
#pragma unroll
        for (int u = 0; u < 4; u++) {
            float4 v = tp[u];
            a[u * 4 + 0] = v.x; a[u * 4 + 1] = v.y;
            a[u * 4 + 2] = v.z; a[u * 4 + 3] = v.w;
        }
    }
    float my_s = FLT_MAX; int my_i = 0x7FFFFFFF;
#pragma unroll
    for (int t = 0; t < SEL; t++) {
        const int idx = sel[t];
        const float4* rp = reinterpret_cast<const float4*>(
            Xtr + (size_t)idx * DIM + lane * 16);
        float dot = 0.f;
#pragma unroll
        for (int u = 0; u < 4; u++) {
            float4 v = rp[u];
            dot = fmaf(a[u * 4 + 0], v.x, dot);
            dot = fmaf(a[u * 4 + 1], v.y, dot);
            dot = fmaf(a[u * 4 + 2], v.z, dot);
            dot = fmaf(a[u * 4 + 3], v.w, dot);
        }
#pragma unroll
        for (int off = 16; off; off >>= 1)
            dot += __shfl_xor_sync(0xFFFFFFFFu, dot, off);
        const float s = fmaf(-2.f, dot, __ldg(&g_x2[idx]));
        if (lane == t) { my_s = s; my_i = idx; }
    }

    // top-5 by (score, index), gather labels, mode
    int lab[5];
#pragma unroll
    for (int r = 0; r < 5; r++) {
        float bs = my_s; int bi = my_i;
#pragma unroll
        for (int off = 16; off; off >>= 1) {
            float os = __shfl_xor_sync(0xFFFFFFFFu, bs, off);
            int   oi = __shfl_xor_sync(0xFFFFFFFFu, bi, off);
            if (os < bs || (os == bs && oi < bi)) { bs = os; bi = oi; }
        }
        if (my_s == bs && my_i == bi) my_s = FLT_MAX;
        unsigned w = (ymode == 1) ? yw[2 * (size_t)bi] : yw[bi];
        lab[r] = (ymode == 2) ? (int)__uint_as_float(w) : (int)w;
    }

    if (lane == 0) {
        int best = 0x7FFFFFFF, bc = 0;
#pragma unroll
        for (int q = 0; q < 5; q++) {
            int c = 0;
#pragma unroll
            for (int r = 0; r < 5; r++) c += (lab[r] == lab[q]);
            if (c > bc || (c == bc && lab[q] < best)) { bc = c; best = lab[q]; }
        }
        out[m] = (float)best;
    }
}

// ---------------------------------------------------------------------------
extern "C" void kernel_launch(void* const* d_in, const int* in_sizes, int n_in,
                              void* d_out, int out_size) {
    const float*    Xtr = (const float*)d_in[0];
    const float*    Xte = (const float*)d_in[1];
    const unsigned* yw  = (const unsigned*)d_in[2];
    float*          out = (float*)d_out;

    cudaFuncSetAttribute(knn_gemm_kernel,
                         cudaFuncAttributeMaxDynamicSharedMemorySize, SMEM_TOTAL);

    conv_train_kernel<<<N_TRAIN / 8, 256>>>(Xtr);
    conv_test_kernel<<<N_TEST / 8, 256>>>(Xte);
    knn_gemm_kernel<<<dim3(N_TEST / 128, SPLITS), 256, SMEM_TOTAL>>>();
    rescue_kernel<<<N_TEST / 8, 256>>>(Xtr, Xte, yw, out);
}